// round 8
// baseline (speedup 1.0000x reference)
#include <cuda_runtime.h>
#include <cuda_fp16.h>
#include <cstdint>

// ============================================================================
// treelstm: c = i*u + sum_n sigmoid(child_h @ W_fh^T + b_fh) * child_c
//           h = o * tanh(c)
// R8: warp tile 64x64 (8 warps, 2m x 4n), CTA 128x256, 4-stage cp.async.
// Tests HMMA-floor vs overhead hypothesis (R4 was 2.8x above rt=8 floor).
// ============================================================================

#define MEM_DIM 1024
#define N_CHILD 16384

// Scratch (device globals — no allocation allowed)
__device__ float d_scr[1024 * 128];                       // [col][rowtile]
__device__ __align__(16) __half d_h16[N_CHILD * MEM_DIM]; // fp16 child_h
__device__ __align__(16) __half d_w16[MEM_DIM * MEM_DIM]; // fp16 W_fh

// ---------------- helpers ----------------
__device__ __forceinline__ uint32_t smem_u32(const void* p) {
    uint32_t a;
    asm("{ .reg .u64 t; cvta.to.shared.u64 t, %1; cvt.u32.u64 %0, t; }"
        : "=r"(a) : "l"(p));
    return a;
}
__device__ __forceinline__ void ldmx4(uint32_t& r0, uint32_t& r1,
                                      uint32_t& r2, uint32_t& r3, uint32_t a) {
    asm volatile("ldmatrix.sync.aligned.m8n8.x4.shared.b16 {%0,%1,%2,%3}, [%4];"
                 : "=r"(r0), "=r"(r1), "=r"(r2), "=r"(r3) : "r"(a));
}
__device__ __forceinline__ void mma16816(float* c, const uint32_t* a,
                                         uint32_t b0, uint32_t b1) {
    asm volatile(
        "mma.sync.aligned.m16n8k16.row.col.f32.f16.f16.f32 "
        "{%0,%1,%2,%3}, {%4,%5,%6,%7}, {%8,%9}, {%0,%1,%2,%3};"
        : "+f"(c[0]), "+f"(c[1]), "+f"(c[2]), "+f"(c[3])
        : "r"(a[0]), "r"(a[1]), "r"(a[2]), "r"(a[3]), "r"(b0), "r"(b1));
}
__device__ __forceinline__ float sigmoidf_(float x) {
    return 1.0f / (1.0f + __expf(-x));
}
#define CP_ASYNC16(dst, src) \
    asm volatile("cp.async.cg.shared.global [%0], [%1], 16;" \
                 :: "r"(dst), "l"(src) : "memory")
#define CP_COMMIT() asm volatile("cp.async.commit_group;" ::: "memory")
#define CP_WAIT(n)  asm volatile("cp.async.wait_group %0;" :: "n"(n) : "memory")

// ---------------- kernel 0: fp32 -> fp16 convert ----------------
__global__ void __launch_bounds__(256)
cvt_kernel(const float* __restrict__ src, __half* __restrict__ dst) {
    size_t i = (size_t)blockIdx.x * 256 + threadIdx.x;   // handles 8 elems
    const float4* s4 = reinterpret_cast<const float4*>(src) + i * 2;
    float4 v0 = s4[0], v1 = s4[1];
    __half2 p0 = __floats2half2_rn(v0.x, v0.y);
    __half2 p1 = __floats2half2_rn(v0.z, v0.w);
    __half2 p2 = __floats2half2_rn(v1.x, v1.y);
    __half2 p3 = __floats2half2_rn(v1.z, v1.w);
    uint4 u;
    u.x = *reinterpret_cast<uint32_t*>(&p0);
    u.y = *reinterpret_cast<uint32_t*>(&p1);
    u.z = *reinterpret_cast<uint32_t*>(&p2);
    u.w = *reinterpret_cast<uint32_t*>(&p3);
    reinterpret_cast<uint4*>(dst)[i] = u;
}

// ---------------- kernel 1: pipelined f-GEMM + colsum ----------------
// grid (4 colTiles, 128 rowTiles), 256 threads (8 warps: 2m x 4n).
// CTA tile 128x256, warp tile 64x64, BK=64, 4-stage cp.async pipeline.
static constexpr int STAGE_BYTES = 49152;        // A 16KB + B 32KB
static constexpr int OFF_BIAS = 196608;          // 256 floats
static constexpr int OFF_CSM = 197632;           // 512 floats
static constexpr int SMEM_BYTES = 199680;

__global__ void __launch_bounds__(256, 1)
fgemm_kernel(const float* __restrict__ child_c, const float* __restrict__ b_fh) {
    extern __shared__ char smem[];
    const uint32_t sb = smem_u32(smem);
    const int tid = threadIdx.x;
    const int lid = tid & 31, wid = tid >> 5;
    const int wm = wid & 1, wn = wid >> 1;       // 2 m-warps x 4 n-warps
    const int colBase = blockIdx.x * 256;
    const int rowBase = blockIdx.y * 128;

    reinterpret_cast<float*>(smem + OFF_BIAS)[tid] = b_fh[colBase + tid];

    // cp.async assignments (12 x 16B per thread per stage)
    const int rA = tid >> 1, ckA = (tid & 1) * 4;   // 128 rows, 4 chunks each
    const int rB = tid;                              // 256 rows, full 128B row
    const __half* gA0 = d_h16 + (size_t)(rowBase + rA) * 1024 + ckA * 8;
    const __half* gB0 = d_w16 + (size_t)(colBase + rB) * 1024;
    const uint32_t dA0 = sb + rA * 128;
    const uint32_t dB0 = sb + 16384 + rB * 128;

    #define ISSUE_STAGE(kc) do { \
        if ((kc) < 16) { \
            uint32_t so = (uint32_t)(((kc) & 3) * STAGE_BYTES); \
            _Pragma("unroll") \
            for (int j = 0; j < 4; j++) \
                CP_ASYNC16(dA0 + so + (((ckA + j) ^ (rA & 7)) << 4), \
                           gA0 + (kc) * 64 + j * 8); \
            _Pragma("unroll") \
            for (int j = 0; j < 8; j++) \
                CP_ASYNC16(dB0 + so + ((j ^ (rB & 7)) << 4), \
                           gB0 + (kc) * 64 + j * 8); \
        } \
        CP_COMMIT(); \
    } while (0)

    float acc[4][8][4];
    #pragma unroll
    for (int mf = 0; mf < 4; mf++)
        #pragma unroll
        for (int nf = 0; nf < 8; nf++)
            #pragma unroll
            for (int v = 0; v < 4; v++) acc[mf][nf][v] = 0.f;

    ISSUE_STAGE(0); ISSUE_STAGE(1); ISSUE_STAGE(2);

    for (int kc = 0; kc < 16; kc++) {
        CP_WAIT(2);
        __syncthreads();
        ISSUE_STAGE(kc + 3);

        const uint32_t au = sb + (kc & 3) * STAGE_BYTES;
        const uint32_t bu = au + 16384;
        #pragma unroll
        for (int ks = 0; ks < 4; ks++) {
            const int chunk = ks * 2 + (lid >> 4);
            uint32_t a[4][4], b[4][4];
            #pragma unroll
            for (int mf = 0; mf < 4; mf++) {
                int r = wm * 64 + mf * 16 + (lid & 15);
                ldmx4(a[mf][0], a[mf][1], a[mf][2], a[mf][3],
                      au + r * 128 + ((chunk ^ (r & 7)) << 4));
            }
            #pragma unroll
            for (int nh = 0; nh < 4; nh++) {
                int r = wn * 64 + nh * 16 + (lid & 15);
                ldmx4(b[nh][0], b[nh][1], b[nh][2], b[nh][3],
                      bu + r * 128 + ((chunk ^ (r & 7)) << 4));
            }
            #pragma unroll
            for (int mf = 0; mf < 4; mf++)
                #pragma unroll
                for (int nf = 0; nf < 8; nf++)
                    mma16816(acc[mf][nf], a[mf],
                             b[nf >> 1][nf & 1], b[nf >> 1][(nf & 1) + 2]);
        }
    }
    __syncthreads();

    // ---- epilogue: f = sigmoid(z + b); colsum over rows of f*child_c ----
    const float* bias = reinterpret_cast<const float*>(smem + OFF_BIAS);
    const int g = lid >> 2, tg = lid & 3;
    float cs0[8], cs1[8];
    #pragma unroll
    for (int nf = 0; nf < 8; nf++) {
        const int c0 = wn * 64 + nf * 8 + tg * 2;
        const float b0 = bias[c0], b1 = bias[c0 + 1];
        float s0 = 0.f, s1 = 0.f;
        #pragma unroll
        for (int mf = 0; mf < 4; mf++) {
            const int r0 = rowBase + wm * 64 + mf * 16 + g;
            const float* cc = child_c + (size_t)r0 * 1024 + colBase + c0;
            float2 cA = *reinterpret_cast<const float2*>(cc);
            float2 cB = *reinterpret_cast<const float2*>(cc + 8 * 1024);
            s0 += sigmoidf_(acc[mf][nf][0] + b0) * cA.x;
            s1 += sigmoidf_(acc[mf][nf][1] + b1) * cA.y;
            s0 += sigmoidf_(acc[mf][nf][2] + b0) * cB.x;
            s1 += sigmoidf_(acc[mf][nf][3] + b1) * cB.y;
        }
        #pragma unroll
        for (int off = 4; off <= 16; off <<= 1) {
            s0 += __shfl_xor_sync(0xffffffffu, s0, off);
            s1 += __shfl_xor_sync(0xffffffffu, s1, off);
        }
        cs0[nf] = s0;
        cs1[nf] = s1;
    }
    float* csm = reinterpret_cast<float*>(smem + OFF_CSM);
    if (g == 0) {
        #pragma unroll
        for (int nf = 0; nf < 8; nf++) {
            csm[wm * 256 + wn * 64 + nf * 8 + tg * 2] = cs0[nf];
            csm[wm * 256 + wn * 64 + nf * 8 + tg * 2 + 1] = cs1[nf];
        }
    }
    __syncthreads();
    d_scr[(size_t)(colBase + tid) * 128 + blockIdx.y] = csm[tid] + csm[256 + tid];
}

// ---------------- kernel 2: gates + reduce + combine ----------------
__global__ void __launch_bounds__(128)
final_kernel(float* __restrict__ out, const float* __restrict__ hsum,
             const float* __restrict__ W_ih, const float* __restrict__ b_ih,
             const float* __restrict__ W_uh, const float* __restrict__ b_uh,
             const float* __restrict__ W_oh, const float* __restrict__ b_oh) {
    const int j = blockIdx.x;
    const int tid = threadIdx.x, wid = tid >> 5, lid = tid & 31;
    __shared__ float red[4];

    float s = 0.f;
    if (wid < 3) {
        const float* W = (wid == 0) ? W_ih : ((wid == 1) ? W_uh : W_oh);
        const float4* Wr = reinterpret_cast<const float4*>(W + (size_t)j * 1024);
        const float4* h4 = reinterpret_cast<const float4*>(hsum);
        #pragma unroll
        for (int st = 0; st < 8; st++) {
            float4 w = Wr[lid + st * 32];
            float4 h = h4[lid + st * 32];
            s += w.x * h.x + w.y * h.y + w.z * h.z + w.w * h.w;
        }
    } else {
        float4 v = reinterpret_cast<const float4*>(d_scr + (size_t)j * 128)[lid];
        s = v.x + v.y + v.z + v.w;
    }
    #pragma unroll
    for (int off = 16; off; off >>= 1) s += __shfl_xor_sync(0xffffffffu, s, off);
    if (lid == 0) red[wid] = s;
    __syncthreads();
    if (tid == 0) {
        float i = sigmoidf_(red[0] + b_ih[j]);
        float u = tanhf(red[1] + b_uh[j]);
        float o = sigmoidf_(red[2] + b_oh[j]);
        float c = i * u + red[3];
        out[j] = c;
        out[1024 + j] = o * tanhf(c);
    }
}

// ---------------- launch ----------------
extern "C" void kernel_launch(void* const* d_in, const int* in_sizes, int n_in,
                              void* d_out, int out_size) {
    (void)in_sizes; (void)n_in; (void)out_size;
    const float* child_c = (const float*)d_in[0];
    const float* child_h = (const float*)d_in[1];
    const float* hsum    = (const float*)d_in[2];
    const float* W_ih    = (const float*)d_in[3];
    const float* b_ih    = (const float*)d_in[4];
    const float* W_fh    = (const float*)d_in[5];
    const float* b_fh    = (const float*)d_in[6];
    const float* W_uh    = (const float*)d_in[7];
    const float* b_uh    = (const float*)d_in[8];
    const float* W_oh    = (const float*)d_in[9];
    const float* b_oh    = (const float*)d_in[10];
    float* out = (float*)d_out;

    __half* h16p = nullptr;
    __half* w16p = nullptr;
    cudaGetSymbolAddress((void**)&h16p, d_h16);
    cudaGetSymbolAddress((void**)&w16p, d_w16);

    cudaFuncSetAttribute(fgemm_kernel, cudaFuncAttributeMaxDynamicSharedMemorySize,
                         SMEM_BYTES);

    cvt_kernel<<<(N_CHILD * MEM_DIM) / (256 * 8), 256>>>(child_h, h16p);
    cvt_kernel<<<(MEM_DIM * MEM_DIM) / (256 * 8), 256>>>(W_fh, w16p);
    fgemm_kernel<<<dim3(4, 128), 256, SMEM_BYTES>>>(child_c, b_fh);
    final_kernel<<<1024, 128>>>(out, hsum, W_ih, b_ih, W_uh, b_uh, W_oh, b_oh);
}

// round 9
// speedup vs baseline: 1.3042x; 1.3042x over previous
#include <cuda_runtime.h>
#include <cuda_fp16.h>
#include <cstdint>

// ============================================================================
// treelstm: c = i*u + sum_n sigmoid(child_h @ W_fh^T + b_fh) * child_c
//           h = o * tanh(c)
// R9: CTA 128x128, 16 warps (4m x 4n), warp tile 32x32, 4-stage cp.async.
// MMA: f16 accumulate in K=32 windows, promoted to fp32 master accumulators
// (tests whether the legacy-HMMA f32-acc path is de-rated on sm_103).
// ============================================================================

#define MEM_DIM 1024
#define N_CHILD 16384

// Scratch (device globals — no allocation allowed)
__device__ float d_scr[1024 * 128];                       // [col][rowtile]
__device__ __align__(16) __half d_h16[N_CHILD * MEM_DIM]; // fp16 child_h
__device__ __align__(16) __half d_w16[MEM_DIM * MEM_DIM]; // fp16 W_fh

// ---------------- helpers ----------------
__device__ __forceinline__ uint32_t smem_u32(const void* p) {
    uint32_t a;
    asm("{ .reg .u64 t; cvta.to.shared.u64 t, %1; cvt.u32.u64 %0, t; }"
        : "=r"(a) : "l"(p));
    return a;
}
__device__ __forceinline__ void ldmx4(uint32_t& r0, uint32_t& r1,
                                      uint32_t& r2, uint32_t& r3, uint32_t a) {
    asm volatile("ldmatrix.sync.aligned.m8n8.x4.shared.b16 {%0,%1,%2,%3}, [%4];"
                 : "=r"(r0), "=r"(r1), "=r"(r2), "=r"(r3) : "r"(a));
}
// f16-accumulator MMA, zero C (window start)
__device__ __forceinline__ void mma_h_zc(uint32_t* d, const uint32_t* a,
                                         uint32_t b0, uint32_t b1) {
    asm volatile(
        "mma.sync.aligned.m16n8k16.row.col.f16.f16.f16.f16 "
        "{%0,%1}, {%2,%3,%4,%5}, {%6,%7}, {%8,%9};"
        : "=r"(d[0]), "=r"(d[1])
        : "r"(a[0]), "r"(a[1]), "r"(a[2]), "r"(a[3]), "r"(b0), "r"(b1),
          "r"(0u), "r"(0u));
}
// f16-accumulator MMA, chained C
__device__ __forceinline__ void mma_h(uint32_t* d, const uint32_t* a,
                                      uint32_t b0, uint32_t b1) {
    asm volatile(
        "mma.sync.aligned.m16n8k16.row.col.f16.f16.f16.f16 "
        "{%0,%1}, {%2,%3,%4,%5}, {%6,%7}, {%0,%1};"
        : "+r"(d[0]), "+r"(d[1])
        : "r"(a[0]), "r"(a[1]), "r"(a[2]), "r"(a[3]), "r"(b0), "r"(b1));
}
__device__ __forceinline__ float sigmoidf_(float x) {
    return 1.0f / (1.0f + __expf(-x));
}
#define CP_ASYNC16(dst, src) \
    asm volatile("cp.async.cg.shared.global [%0], [%1], 16;" \
                 :: "r"(dst), "l"(src) : "memory")
#define CP_COMMIT() asm volatile("cp.async.commit_group;" ::: "memory")
#define CP_WAIT(n)  asm volatile("cp.async.wait_group %0;" :: "n"(n) : "memory")

// ---------------- kernel 0: fp32 -> fp16 convert ----------------
__global__ void __launch_bounds__(256)
cvt_kernel(const float* __restrict__ src, __half* __restrict__ dst) {
    size_t i = (size_t)blockIdx.x * 256 + threadIdx.x;   // handles 8 elems
    const float4* s4 = reinterpret_cast<const float4*>(src) + i * 2;
    float4 v0 = s4[0], v1 = s4[1];
    __half2 p0 = __floats2half2_rn(v0.x, v0.y);
    __half2 p1 = __floats2half2_rn(v0.z, v0.w);
    __half2 p2 = __floats2half2_rn(v1.x, v1.y);
    __half2 p3 = __floats2half2_rn(v1.z, v1.w);
    uint4 u;
    u.x = *reinterpret_cast<uint32_t*>(&p0);
    u.y = *reinterpret_cast<uint32_t*>(&p1);
    u.z = *reinterpret_cast<uint32_t*>(&p2);
    u.w = *reinterpret_cast<uint32_t*>(&p3);
    reinterpret_cast<uint4*>(dst)[i] = u;
}

// ---------------- kernel 1: pipelined f-GEMM + colsum ----------------
// grid (8 colTiles, 128 rowTiles), 512 threads (16 warps: 4m x 4n).
// CTA tile 128x128, warp tile 32x32, BK=64, 4-stage cp.async pipeline.
static constexpr int STAGE_BYTES = 32768;        // A 16KB + B 16KB
static constexpr int OFF_BIAS = 131072;          // 128 floats
static constexpr int OFF_CSM = 131584;           // 512 floats
static constexpr int SMEM_BYTES = 133632;

__global__ void __launch_bounds__(512, 1)
fgemm_kernel(const float* __restrict__ child_c, const float* __restrict__ b_fh) {
    extern __shared__ char smem[];
    const uint32_t sb = smem_u32(smem);
    const int tid = threadIdx.x;
    const int lid = tid & 31, wid = tid >> 5;
    const int wm = wid & 3, wn = wid >> 2;       // 4 m-warps x 4 n-warps
    const int colBase = blockIdx.x * 128;
    const int rowBase = blockIdx.y * 128;

    if (tid < 128)
        reinterpret_cast<float*>(smem + OFF_BIAS)[tid] = b_fh[colBase + tid];

    // cp.async assignments (4 x 16B per thread per stage: 2 A + 2 B)
    const int rL = tid >> 2, ckL = (tid & 3) * 2;   // 128 rows, 2 chunks each
    const __half* gA0 = d_h16 + (size_t)(rowBase + rL) * 1024 + ckL * 8;
    const __half* gB0 = d_w16 + (size_t)(colBase + rL) * 1024 + ckL * 8;
    const uint32_t dA0 = sb + rL * 128;
    const uint32_t dB0 = sb + 16384 + rL * 128;

    #define ISSUE_STAGE(kc) do { \
        if ((kc) < 16) { \
            uint32_t so = (uint32_t)(((kc) & 3) * STAGE_BYTES); \
            _Pragma("unroll") \
            for (int j = 0; j < 2; j++) \
                CP_ASYNC16(dA0 + so + (((ckL + j) ^ (rL & 7)) << 4), \
                           gA0 + (kc) * 64 + j * 8); \
            _Pragma("unroll") \
            for (int j = 0; j < 2; j++) \
                CP_ASYNC16(dB0 + so + (((ckL + j) ^ (rL & 7)) << 4), \
                           gB0 + (kc) * 64 + j * 8); \
        } \
        CP_COMMIT(); \
    } while (0)

    float acc[2][4][4];                          // fp32 master accumulators
    #pragma unroll
    for (int mf = 0; mf < 2; mf++)
        #pragma unroll
        for (int nf = 0; nf < 4; nf++)
            #pragma unroll
            for (int v = 0; v < 4; v++) acc[mf][nf][v] = 0.f;

    ISSUE_STAGE(0); ISSUE_STAGE(1); ISSUE_STAGE(2);

    for (int kc = 0; kc < 16; kc++) {
        CP_WAIT(2);
        __syncthreads();
        ISSUE_STAGE(kc + 3);

        const uint32_t au = sb + (kc & 3) * STAGE_BYTES;
        const uint32_t bu = au + 16384;
        #pragma unroll
        for (int w = 0; w < 2; w++) {            // K=32 window
            uint32_t hacc[2][4][2];
            #pragma unroll
            for (int s = 0; s < 2; s++) {
                const int ks = w * 2 + s;
                const int chunk = ks * 2 + (lid >> 4);
                uint32_t a[2][4], b[2][4];
                #pragma unroll
                for (int mf = 0; mf < 2; mf++) {
                    int r = wm * 32 + mf * 16 + (lid & 15);
                    ldmx4(a[mf][0], a[mf][1], a[mf][2], a[mf][3],
                          au + r * 128 + ((chunk ^ (r & 7)) << 4));
                }
                #pragma unroll
                for (int nh = 0; nh < 2; nh++) {
                    int r = wn * 32 + nh * 16 + (lid & 15);
                    ldmx4(b[nh][0], b[nh][1], b[nh][2], b[nh][3],
                          bu + r * 128 + ((chunk ^ (r & 7)) << 4));
                }
                #pragma unroll
                for (int mf = 0; mf < 2; mf++)
                    #pragma unroll
                    for (int nf = 0; nf < 4; nf++) {
                        if (s == 0)
                            mma_h_zc(hacc[mf][nf], a[mf],
                                     b[nf >> 1][nf & 1], b[nf >> 1][(nf & 1) + 2]);
                        else
                            mma_h(hacc[mf][nf], a[mf],
                                  b[nf >> 1][nf & 1], b[nf >> 1][(nf & 1) + 2]);
                    }
            }
            // promote window into fp32 master accumulators
            #pragma unroll
            for (int mf = 0; mf < 2; mf++)
                #pragma unroll
                for (int nf = 0; nf < 4; nf++) {
                    float2 f0 = __half22float2(
                        *reinterpret_cast<__half2*>(&hacc[mf][nf][0]));
                    float2 f1 = __half22float2(
                        *reinterpret_cast<__half2*>(&hacc[mf][nf][1]));
                    acc[mf][nf][0] += f0.x;
                    acc[mf][nf][1] += f0.y;
                    acc[mf][nf][2] += f1.x;
                    acc[mf][nf][3] += f1.y;
                }
        }
    }
    __syncthreads();

    // ---- epilogue: f = sigmoid(z + b); colsum over rows of f*child_c ----
    const float* bias = reinterpret_cast<const float*>(smem + OFF_BIAS);
    const int g = lid >> 2, tg = lid & 3;
    float cs0[4], cs1[4];
    #pragma unroll
    for (int nf = 0; nf < 4; nf++) {
        const int c0 = wn * 32 + nf * 8 + tg * 2;
        const float b0 = bias[c0], b1 = bias[c0 + 1];
        float s0 = 0.f, s1 = 0.f;
        #pragma unroll
        for (int mf = 0; mf < 2; mf++) {
            const int r0 = rowBase + wm * 32 + mf * 16 + g;
            const float* cc = child_c + (size_t)r0 * 1024 + colBase + c0;
            float2 cA = *reinterpret_cast<const float2*>(cc);
            float2 cB = *reinterpret_cast<const float2*>(cc + 8 * 1024);
            s0 += sigmoidf_(acc[mf][nf][0] + b0) * cA.x;
            s1 += sigmoidf_(acc[mf][nf][1] + b1) * cA.y;
            s0 += sigmoidf_(acc[mf][nf][2] + b0) * cB.x;
            s1 += sigmoidf_(acc[mf][nf][3] + b1) * cB.y;
        }
        #pragma unroll
        for (int off = 4; off <= 16; off <<= 1) {
            s0 += __shfl_xor_sync(0xffffffffu, s0, off);
            s1 += __shfl_xor_sync(0xffffffffu, s1, off);
        }
        cs0[nf] = s0;
        cs1[nf] = s1;
    }
    float* csm = reinterpret_cast<float*>(smem + OFF_CSM);
    if (g == 0) {
        #pragma unroll
        for (int nf = 0; nf < 4; nf++) {
            csm[wm * 128 + wn * 32 + nf * 8 + tg * 2] = cs0[nf];
            csm[wm * 128 + wn * 32 + nf * 8 + tg * 2 + 1] = cs1[nf];
        }
    }
    __syncthreads();
    if (tid < 128)
        d_scr[(size_t)(colBase + tid) * 128 + blockIdx.y] =
            csm[tid] + csm[128 + tid] + csm[256 + tid] + csm[384 + tid];
}

// ---------------- kernel 2: gates + reduce + combine ----------------
__global__ void __launch_bounds__(128)
final_kernel(float* __restrict__ out, const float* __restrict__ hsum,
             const float* __restrict__ W_ih, const float* __restrict__ b_ih,
             const float* __restrict__ W_uh, const float* __restrict__ b_uh,
             const float* __restrict__ W_oh, const float* __restrict__ b_oh) {
    const int j = blockIdx.x;
    const int tid = threadIdx.x, wid = tid >> 5, lid = tid & 31;
    __shared__ float red[4];

    float s = 0.f;
    if (wid < 3) {
        const float* W = (wid == 0) ? W_ih : ((wid == 1) ? W_uh : W_oh);
        const float4* Wr = reinterpret_cast<const float4*>(W + (size_t)j * 1024);
        const float4* h4 = reinterpret_cast<const float4*>(hsum);
        #pragma unroll
        for (int st = 0; st < 8; st++) {
            float4 w = Wr[lid + st * 32];
            float4 h = h4[lid + st * 32];
            s += w.x * h.x + w.y * h.y + w.z * h.z + w.w * h.w;
        }
    } else {
        float4 v = reinterpret_cast<const float4*>(d_scr + (size_t)j * 128)[lid];
        s = v.x + v.y + v.z + v.w;
    }
    #pragma unroll
    for (int off = 16; off; off >>= 1) s += __shfl_xor_sync(0xffffffffu, s, off);
    if (lid == 0) red[wid] = s;
    __syncthreads();
    if (tid == 0) {
        float i = sigmoidf_(red[0] + b_ih[j]);
        float u = tanhf(red[1] + b_uh[j]);
        float o = sigmoidf_(red[2] + b_oh[j]);
        float c = i * u + red[3];
        out[j] = c;
        out[1024 + j] = o * tanhf(c);
    }
}

// ---------------- launch ----------------
extern "C" void kernel_launch(void* const* d_in, const int* in_sizes, int n_in,
                              void* d_out, int out_size) {
    (void)in_sizes; (void)n_in; (void)out_size;
    const float* child_c = (const float*)d_in[0];
    const float* child_h = (const float*)d_in[1];
    const float* hsum    = (const float*)d_in[2];
    const float* W_ih    = (const float*)d_in[3];
    const float* b_ih    = (const float*)d_in[4];
    const float* W_fh    = (const float*)d_in[5];
    const float* b_fh    = (const float*)d_in[6];
    const float* W_uh    = (const float*)d_in[7];
    const float* b_uh    = (const float*)d_in[8];
    const float* W_oh    = (const float*)d_in[9];
    const float* b_oh    = (const float*)d_in[10];
    float* out = (float*)d_out;

    __half* h16p = nullptr;
    __half* w16p = nullptr;
    cudaGetSymbolAddress((void**)&h16p, d_h16);
    cudaGetSymbolAddress((void**)&w16p, d_w16);

    cudaFuncSetAttribute(fgemm_kernel, cudaFuncAttributeMaxDynamicSharedMemorySize,
                         SMEM_BYTES);

    cvt_kernel<<<(N_CHILD * MEM_DIM) / (256 * 8), 256>>>(child_h, h16p);
    cvt_kernel<<<(MEM_DIM * MEM_DIM) / (256 * 8), 256>>>(W_fh, w16p);
    fgemm_kernel<<<dim3(8, 128), 512, SMEM_BYTES>>>(child_c, b_fh);
    final_kernel<<<1024, 128>>>(out, hsum, W_ih, b_ih, W_uh, b_uh, W_oh, b_oh);
}

// round 11
// speedup vs baseline: 1.5755x; 1.2080x over previous
#include <cuda_runtime.h>
#include <cuda_fp16.h>
#include <cstdint>

// ============================================================================
// treelstm: c = i*u + sum_n sigmoid(child_h @ W_fh^T + b_fh) * child_c
//           h = o * tanh(c)
// R10: persistent 148-CTA fgemm, 1024 tiles 128x128 (tail 16%->1%),
// continuous cp.async pipeline across tiles (no drain at tile switch),
// f32-acc fp16 HMMA (validated 4.58e-4), merged cvt kernel.
// ============================================================================

#define MEM_DIM 1024
#define N_CHILD 16384
#define NUM_CTAS 148
#define NUM_TILES 1024          // 128 row tiles x 8 col tiles

// Scratch (device globals — no allocation allowed)
__device__ float d_scr[1024 * 128];                       // [col][rowtile]
__device__ __align__(16) __half d_h16[N_CHILD * MEM_DIM]; // fp16 child_h
__device__ __align__(16) __half d_w16[MEM_DIM * MEM_DIM]; // fp16 W_fh

// ---------------- helpers ----------------
__device__ __forceinline__ uint32_t smem_u32(const void* p) {
    uint32_t a;
    asm("{ .reg .u64 t; cvta.to.shared.u64 t, %1; cvt.u32.u64 %0, t; }"
        : "=r"(a) : "l"(p));
    return a;
}
__device__ __forceinline__ void ldmx4(uint32_t& r0, uint32_t& r1,
                                      uint32_t& r2, uint32_t& r3, uint32_t a) {
    asm volatile("ldmatrix.sync.aligned.m8n8.x4.shared.b16 {%0,%1,%2,%3}, [%4];"
                 : "=r"(r0), "=r"(r1), "=r"(r2), "=r"(r3) : "r"(a));
}
__device__ __forceinline__ void mma16816(float* c, const uint32_t* a,
                                         uint32_t b0, uint32_t b1) {
    asm volatile(
        "mma.sync.aligned.m16n8k16.row.col.f32.f16.f16.f32 "
        "{%0,%1,%2,%3}, {%4,%5,%6,%7}, {%8,%9}, {%0,%1,%2,%3};"
        : "+f"(c[0]), "+f"(c[1]), "+f"(c[2]), "+f"(c[3])
        : "r"(a[0]), "r"(a[1]), "r"(a[2]), "r"(a[3]), "r"(b0), "r"(b1));
}
__device__ __forceinline__ float sigmoidf_(float x) {
    return 1.0f / (1.0f + __expf(-x));
}
#define CP_ASYNC16(dst, src) \
    asm volatile("cp.async.cg.shared.global [%0], [%1], 16;" \
                 :: "r"(dst), "l"(src) : "memory")
#define CP_COMMIT() asm volatile("cp.async.commit_group;" ::: "memory")
#define CP_WAIT(n)  asm volatile("cp.async.wait_group %0;" :: "n"(n) : "memory")

// ---------------- kernel 0: fp32 -> fp16 convert (both arrays) ----------------
// blocks [0, 8192): child_h (16384x1024); blocks [8192, 8704): W_fh (1024x1024)
__global__ void __launch_bounds__(256)
cvt_kernel(const float* __restrict__ child_h, const float* __restrict__ W_fh) {
    const float* src;
    __half* dst;
    size_t i;
    if (blockIdx.x < 8192) {
        src = child_h;
        dst = d_h16;
        i = (size_t)blockIdx.x * 256 + threadIdx.x;
    } else {
        src = W_fh;
        dst = d_w16;
        i = (size_t)(blockIdx.x - 8192) * 256 + threadIdx.x;
    }
    const float4* s4 = reinterpret_cast<const float4*>(src) + i * 2;
    float4 v0 = s4[0], v1 = s4[1];
    __half2 p0 = __floats2half2_rn(v0.x, v0.y);
    __half2 p1 = __floats2half2_rn(v0.z, v0.w);
    __half2 p2 = __floats2half2_rn(v1.x, v1.y);
    __half2 p3 = __floats2half2_rn(v1.z, v1.w);
    uint4 u;
    u.x = *reinterpret_cast<uint32_t*>(&p0);
    u.y = *reinterpret_cast<uint32_t*>(&p1);
    u.z = *reinterpret_cast<uint32_t*>(&p2);
    u.w = *reinterpret_cast<uint32_t*>(&p3);
    reinterpret_cast<uint4*>(dst)[i] = u;
}

// ---------------- kernel 1: persistent pipelined f-GEMM + colsum ----------------
// 148 CTAs x 512 threads (16 warps: 4m x 4n). Tile 128x128, warp tile 32x32,
// BK=64, 4-stage cp.async pipeline continuous across tiles.
static constexpr int STAGE_BYTES = 32768;        // A 16KB + B 16KB
static constexpr int OFF_CSM = 131072;           // 512 floats
static constexpr int SMEM_BYTES = 133120;

__global__ void __launch_bounds__(512, 1)
fgemm_kernel(const float* __restrict__ child_c, const float* __restrict__ b_fh) {
    extern __shared__ char smem[];
    const uint32_t sb = smem_u32(smem);
    const int tid = threadIdx.x;
    const int lid = tid & 31, wid = tid >> 5;
    const int wm = wid & 3, wn = wid >> 2;       // 4 m-warps x 4 n-warps
    const int cta = blockIdx.x;

    // number of tiles this CTA owns
    int nt = 0;
    for (int t = cta; t < NUM_TILES; t += NUM_CTAS) nt++;
    const int total_chunks = nt * 16;

    // per-thread load slots: 2 A rows-chunks + 2 B rows-chunks (4 x 16B)
    const int rL = tid >> 2, ckL = (tid & 3) * 2;   // 128 rows, 2 chunks each
    const uint32_t dA0 = sb + rL * 128 + (((ckL) ^ (rL & 7)) << 4);
    const uint32_t dA1 = sb + rL * 128 + (((ckL + 1) ^ (rL & 7)) << 4);
    const uint32_t dB0 = sb + 16384 + rL * 128 + (((ckL) ^ (rL & 7)) << 4);
    const uint32_t dB1 = sb + 16384 + rL * 128 + (((ckL + 1) ^ (rL & 7)) << 4);

    // issue global chunk l of this CTA's stream (always commits)
    #define ISSUE(l) do { \
        if ((l) < total_chunks) { \
            int t_ = cta + ((l) >> 4) * NUM_CTAS; \
            int kc_ = (l) & 15; \
            uint32_t so = (uint32_t)(((l) & 3) * STAGE_BYTES); \
            const __half* ga = d_h16 + \
                (size_t)(((t_ >> 3) * 128) + rL) * 1024 + kc_ * 64 + ckL * 8; \
            const __half* gb = d_w16 + \
                (size_t)(((t_ & 7) * 128) + rL) * 1024 + kc_ * 64 + ckL * 8; \
            CP_ASYNC16(dA0 + so, ga); \
            CP_ASYNC16(dA1 + so, ga + 8); \
            CP_ASYNC16(dB0 + so, gb); \
            CP_ASYNC16(dB1 + so, gb + 8); \
        } \
        CP_COMMIT(); \
    } while (0)

    ISSUE(0); ISSUE(1); ISSUE(2);

    float acc[2][4][4];
    for (int ti = 0; ti < nt; ti++) {
        const int t = cta + ti * NUM_CTAS;
        const int rowBase = (t >> 3) * 128;
        const int colBase = (t & 7) * 128;

        #pragma unroll
        for (int mf = 0; mf < 2; mf++)
            #pragma unroll
            for (int nf = 0; nf < 4; nf++)
                #pragma unroll
                for (int v = 0; v < 4; v++) acc[mf][nf][v] = 0.f;

        for (int kc = 0; kc < 16; kc++) {
            CP_WAIT(2);
            __syncthreads();
            ISSUE(ti * 16 + kc + 3);

            const uint32_t au = sb + (kc & 3) * STAGE_BYTES;
            const uint32_t bu = au + 16384;
            #pragma unroll
            for (int ks = 0; ks < 4; ks++) {
                const int chunk = ks * 2 + (lid >> 4);
                uint32_t a[2][4], b[2][4];
                #pragma unroll
                for (int mf = 0; mf < 2; mf++) {
                    int r = wm * 32 + mf * 16 + (lid & 15);
                    ldmx4(a[mf][0], a[mf][1], a[mf][2], a[mf][3],
                          au + r * 128 + ((chunk ^ (r & 7)) << 4));
                }
                #pragma unroll
                for (int nh = 0; nh < 2; nh++) {
                    int r = wn * 32 + nh * 16 + (lid & 15);
                    ldmx4(b[nh][0], b[nh][1], b[nh][2], b[nh][3],
                          bu + r * 128 + ((chunk ^ (r & 7)) << 4));
                }
                #pragma unroll
                for (int mf = 0; mf < 2; mf++)
                    #pragma unroll
                    for (int nf = 0; nf < 4; nf++)
                        mma16816(acc[mf][nf], a[mf],
                                 b[nf >> 1][nf & 1], b[nf >> 1][(nf & 1) + 2]);
            }
        }
        __syncthreads();   // stage buffers for next tile already in flight;
                           // epilogue touches only CSM / regs / gmem

        // ---- epilogue: f = sigmoid(z + b); colsum over rows of f*child_c ----
        const int g = lid >> 2, tg = lid & 3;
        float cs0[4], cs1[4];
        #pragma unroll
        for (int nf = 0; nf < 4; nf++) {
            const int c0 = colBase + wn * 32 + nf * 8 + tg * 2;
            const float b0 = __ldg(b_fh + c0), b1 = __ldg(b_fh + c0 + 1);
            float s0 = 0.f, s1 = 0.f;
            #pragma unroll
            for (int mf = 0; mf < 2; mf++) {
                const int r0 = rowBase + wm * 32 + mf * 16 + g;
                const float* cc = child_c + (size_t)r0 * 1024 + c0;
                float2 cA = *reinterpret_cast<const float2*>(cc);
                float2 cB = *reinterpret_cast<const float2*>(cc + 8 * 1024);
                s0 += sigmoidf_(acc[mf][nf][0] + b0) * cA.x;
                s1 += sigmoidf_(acc[mf][nf][1] + b1) * cA.y;
                s0 += sigmoidf_(acc[mf][nf][2] + b0) * cB.x;
                s1 += sigmoidf_(acc[mf][nf][3] + b1) * cB.y;
            }
            #pragma unroll
            for (int off = 4; off <= 16; off <<= 1) {
                s0 += __shfl_xor_sync(0xffffffffu, s0, off);
                s1 += __shfl_xor_sync(0xffffffffu, s1, off);
            }
            cs0[nf] = s0;
            cs1[nf] = s1;
        }
        float* csm = reinterpret_cast<float*>(smem + OFF_CSM);
        if (g == 0) {
            #pragma unroll
            for (int nf = 0; nf < 4; nf++) {
                csm[wm * 128 + wn * 32 + nf * 8 + tg * 2] = cs0[nf];
                csm[wm * 128 + wn * 32 + nf * 8 + tg * 2 + 1] = cs1[nf];
            }
        }
        __syncthreads();
        if (tid < 128)
            d_scr[(size_t)(colBase + tid) * 128 + (t >> 3)] =
                csm[tid] + csm[128 + tid] + csm[256 + tid] + csm[384 + tid];
        __syncthreads();
    }
}

// ---------------- kernel 2: gates + reduce + combine ----------------
__global__ void __launch_bounds__(128)
final_kernel(float* __restrict__ out, const float* __restrict__ hsum,
             const float* __restrict__ W_ih, const float* __restrict__ b_ih,
             const float* __restrict__ W_uh, const float* __restrict__ b_uh,
             const float* __restrict__ W_oh, const float* __restrict__ b_oh) {
    const int j = blockIdx.x;
    const int tid = threadIdx.x, wid = tid >> 5, lid = tid & 31;
    __shared__ float red[4];

    float s = 0.f;
    if (wid < 3) {
        const float* W = (wid == 0) ? W_ih : ((wid == 1) ? W_uh : W_oh);
        const float4* Wr = reinterpret_cast<const float4*>(W + (size_t)j * 1024);
        const float4* h4 = reinterpret_cast<const float4*>(hsum);
        #pragma unroll
        for (int st = 0; st < 8; st++) {
            float4 w = Wr[lid + st * 32];
            float4 h = h4[lid + st * 32];
            s += w.x * h.x + w.y * h.y + w.z * h.z + w.w * h.w;
        }
    } else {
        float4 v = reinterpret_cast<const float4*>(d_scr + (size_t)j * 128)[lid];
        s = v.x + v.y + v.z + v.w;
    }
    #pragma unroll
    for (int off = 16; off; off >>= 1) s += __shfl_xor_sync(0xffffffffu, s, off);
    if (lid == 0) red[wid] = s;
    __syncthreads();
    if (tid == 0) {
        float i = sigmoidf_(red[0] + b_ih[j]);
        float u = tanhf(red[1] + b_uh[j]);
        float o = sigmoidf_(red[2] + b_oh[j]);
        float c = i * u + red[3];
        out[j] = c;
        out[1024 + j] = o * tanhf(c);
    }
}

// ---------------- launch ----------------
extern "C" void kernel_launch(void* const* d_in, const int* in_sizes, int n_in,
                              void* d_out, int out_size) {
    (void)in_sizes; (void)n_in; (void)out_size;
    const float* child_c = (const float*)d_in[0];
    const float* child_h = (const float*)d_in[1];
    const float* hsum    = (const float*)d_in[2];
    const float* W_ih    = (const float*)d_in[3];
    const float* b_ih    = (const float*)d_in[4];
    const float* W_fh    = (const float*)d_in[5];
    const float* b_fh    = (const float*)d_in[6];
    const float* W_uh    = (const float*)d_in[7];
    const float* b_uh    = (const float*)d_in[8];
    const float* W_oh    = (const float*)d_in[9];
    const float* b_oh    = (const float*)d_in[10];
    float* out = (float*)d_out;

    cudaFuncSetAttribute(fgemm_kernel, cudaFuncAttributeMaxDynamicSharedMemorySize,
                         SMEM_BYTES);

    cvt_kernel<<<8704, 256>>>(child_h, W_fh);
    fgemm_kernel<<<NUM_CTAS, 512, SMEM_BYTES>>>(child_c, b_fh);
    final_kernel<<<1024, 128>>>(out, hsum, W_ih, b_ih, W_uh, b_uh, W_oh, b_oh);
}